// round 4
// baseline (speedup 1.0000x reference)
#include <cuda_runtime.h>
#include <cuda_bf16.h>

// ---------------------------------------------------------------------------
// CombinedGoalObsNetwork — R4: atomic edge kernels (bf16-compressed GINE
// gather) + 4-thread/row unfused MLP layers.
// ---------------------------------------------------------------------------

#define F64 64
#define NSTATE_MAX 65536
#define NTASK_MAX  32768
#define NACT_MAX   32768

__device__ __align__(16) float g_h_task[NTASK_MAX * F64];
__device__ __align__(16) float g_tmp   [NTASK_MAX * F64];
__device__ __align__(16) float g_x1    [NTASK_MAX * F64];
__device__ __align__(16) float g_h2    [NACT_MAX  * F64];
__device__ __align__(16) __nv_bfloat16 g_xs_h[NSTATE_MAX * F64];  // bf16 x_state

// ---------------------------------------------------------------------------
// Convert x_state to bf16 (one pass, 16MB read / 8MB write)
// ---------------------------------------------------------------------------
__global__ void convert_xstate_kernel(const float* __restrict__ x_state, int n_state)
{
    int tot = gridDim.x * blockDim.x;
    int tid = blockIdx.x * blockDim.x + threadIdx.x;
    int n4 = n_state * (F64 / 4);
    const float4* xp = (const float4*)x_state;
    uint2* op = (uint2*)g_xs_h;
    for (int i = tid; i < n4; i += tot) {
        float4 v = __ldg(xp + i);
        __nv_bfloat162 lo = __floats2bfloat162_rn(v.x, v.y);
        __nv_bfloat162 hi = __floats2bfloat162_rn(v.z, v.w);
        uint2 u;
        u.x = *reinterpret_cast<unsigned*>(&lo);
        u.y = *reinterpret_cast<unsigned*>(&hi);
        op[i] = u;
    }
}

// ---------------------------------------------------------------------------
// Init: h_task = x_task ; h2 = x_actor
// ---------------------------------------------------------------------------
__global__ void init_kernel(const float* __restrict__ x_task,
                            const float* __restrict__ x_actor,
                            int n_task, int n_actor)
{
    int tot = gridDim.x * blockDim.x;
    int tid = blockIdx.x * blockDim.x + threadIdx.x;
    int nt4 = n_task * (F64 / 4);
    int na4 = n_actor * (F64 / 4);
    const float4* xt = (const float4*)x_task;
    const float4* xa = (const float4*)x_actor;
    float4* ht = (float4*)g_h_task;
    float4* h2 = (float4*)g_h2;
    for (int i = tid; i < nt4; i += tot) ht[i] = xt[i];
    for (int i = tid; i < na4; i += tot) h2[i] = xa[i];
}

__device__ __forceinline__ void red_add_v4(float* p, float4 v)
{
    asm volatile("red.global.add.v4.f32 [%0], {%1,%2,%3,%4};"
                 :: "l"(p), "f"(v.x), "f"(v.y), "f"(v.z), "f"(v.w)
                 : "memory");
}

// ---------------------------------------------------------------------------
// GINEConv edge kernel: 16 lanes/edge, 4 feats per lane, bf16 gather.
// ---------------------------------------------------------------------------
__global__ void edge_gine_kernel(const float* __restrict__ edge_attr,
                                 const float* __restrict__ We,
                                 const float* __restrict__ be,
                                 const int*   __restrict__ src,
                                 const int*   __restrict__ dst,
                                 int E)
{
    const int lane = threadIdx.x & 15;
    const float4 w0 = __ldg((const float4*)We + lane);
    const float4 w1 = __ldg((const float4*)(We + F64) + lane);
    const float4 bb = __ldg((const float4*)be + lane);

    int g  = (blockIdx.x * blockDim.x + threadIdx.x) >> 4;
    int gs = (gridDim.x * blockDim.x) >> 4;

    #pragma unroll 2
    for (int e = g; e < E; e += gs) {
        const int s = __ldg(src + e);
        const int d = __ldg(dst + e);
        const float2 a = __ldg((const float2*)edge_attr + e);
        const uint2 raw = __ldg((const uint2*)(g_xs_h + (size_t)s * F64) + lane);
        const float2 x01 = __bfloat1622float2(*reinterpret_cast<const __nv_bfloat162*>(&raw.x));
        const float2 x23 = __bfloat1622float2(*reinterpret_cast<const __nv_bfloat162*>(&raw.y));
        float4 v;
        v.x = fmaxf(fmaf(a.x, w0.x, fmaf(a.y, w1.x, x01.x + bb.x)), 0.f);
        v.y = fmaxf(fmaf(a.x, w0.y, fmaf(a.y, w1.y, x01.y + bb.y)), 0.f);
        v.z = fmaxf(fmaf(a.x, w0.z, fmaf(a.y, w1.z, x23.x + bb.z)), 0.f);
        v.w = fmaxf(fmaf(a.x, w0.w, fmaf(a.y, w1.w, x23.y + bb.w)), 0.f);
        red_add_v4(g_h_task + (size_t)d * F64 + lane * 4, v);
    }
}

// ---------------------------------------------------------------------------
// GINConv edge kernel (fp32 gather — precision-critical mixed-sign sum).
// ---------------------------------------------------------------------------
__global__ void edge_gin_kernel(const int* __restrict__ src,
                                const int* __restrict__ dst,
                                int E)
{
    const int lane = threadIdx.x & 15;
    int g  = (blockIdx.x * blockDim.x + threadIdx.x) >> 4;
    int gs = (gridDim.x * blockDim.x) >> 4;

    #pragma unroll 2
    for (int e = g; e < E; e += gs) {
        const int s = __ldg(src + e);
        const int d = __ldg(dst + e);
        const float4 v = *((const float4*)(g_x1 + (size_t)s * F64) + lane);
        red_add_v4(g_h2 + (size_t)d * F64 + lane * 4, v);
    }
}

// ---------------------------------------------------------------------------
// Dense 64x64 layer, 4 threads/row (thread q -> output cols [16q,16q+16)).
// W in SMEM (broadcast LDS). No inter-thread exchange.
// ---------------------------------------------------------------------------
__global__ void layer64_kernel(const float* __restrict__ in,
                               const float* __restrict__ W,
                               const float* __restrict__ b,
                               float* __restrict__ out,
                               int n, int do_relu)
{
    __shared__ float sW[F64 * F64];
    __shared__ float sb[F64];
    for (int i = threadIdx.x; i < F64 * F64; i += blockDim.x) sW[i] = W[i];
    if (threadIdx.x < F64) sb[threadIdx.x] = b[threadIdx.x];
    __syncthreads();

    const int tid = blockIdx.x * blockDim.x + threadIdx.x;
    int row = tid >> 2;
    const int q = tid & 3;
    const bool valid = (row < n);
    if (!valid) row = n - 1;

    const float4* xp = (const float4*)(in + (size_t)row * F64);

    float acc[16];
    #pragma unroll
    for (int j = 0; j < 16; j++) acc[j] = sb[q * 16 + j];

    #pragma unroll
    for (int k4 = 0; k4 < 16; k4++) {
        const float4 xv = __ldg(xp + k4);
        #pragma unroll
        for (int kk = 0; kk < 4; kk++) {
            const float xk = (kk == 0) ? xv.x : (kk == 1) ? xv.y : (kk == 2) ? xv.z : xv.w;
            const float* wr = &sW[(k4 * 4 + kk) * F64 + q * 16];
            #pragma unroll
            for (int j4 = 0; j4 < 4; j4++) {
                const float4 w = *(const float4*)(wr + j4 * 4);
                acc[4*j4+0] = fmaf(xk, w.x, acc[4*j4+0]);
                acc[4*j4+1] = fmaf(xk, w.y, acc[4*j4+1]);
                acc[4*j4+2] = fmaf(xk, w.z, acc[4*j4+2]);
                acc[4*j4+3] = fmaf(xk, w.w, acc[4*j4+3]);
            }
        }
    }

    if (valid) {
        float4* op = (float4*)(out + (size_t)row * F64) + q * 4;
        #pragma unroll
        for (int i = 0; i < 4; i++) {
            float4 v = make_float4(acc[4*i+0], acc[4*i+1], acc[4*i+2], acc[4*i+3]);
            if (do_relu) {
                v.x = fmaxf(v.x, 0.f); v.y = fmaxf(v.y, 0.f);
                v.z = fmaxf(v.z, 0.f); v.w = fmaxf(v.w, 0.f);
            }
            op[i] = v;
        }
    }
}

// ---------------------------------------------------------------------------
// Fused MLP + head: out[row] = relu(in @ W2a + b2a) @ W2b + b2b (64->1)
// 4 threads/row, quad-reduce at the end only.
// ---------------------------------------------------------------------------
__global__ void mlp_head_kernel(const float* __restrict__ in,
                                const float* __restrict__ Wa,
                                const float* __restrict__ ba,
                                const float* __restrict__ wv,
                                const float* __restrict__ bv,
                                float* __restrict__ out, int n)
{
    __shared__ float sA[F64 * F64];
    __shared__ float sba[F64];
    __shared__ float sw[F64];
    for (int i = threadIdx.x; i < F64 * F64; i += blockDim.x) sA[i] = Wa[i];
    if (threadIdx.x < F64) { sba[threadIdx.x] = ba[threadIdx.x]; sw[threadIdx.x] = wv[threadIdx.x]; }
    __syncthreads();

    const int tid = blockIdx.x * blockDim.x + threadIdx.x;
    int row = tid >> 2;
    const int q = tid & 3;
    const bool valid = (row < n);
    if (!valid) row = n - 1;

    const float4* xp = (const float4*)(in + (size_t)row * F64);

    float h[16];
    #pragma unroll
    for (int j = 0; j < 16; j++) h[j] = sba[q * 16 + j];

    #pragma unroll
    for (int k4 = 0; k4 < 16; k4++) {
        const float4 xv = __ldg(xp + k4);
        #pragma unroll
        for (int kk = 0; kk < 4; kk++) {
            const float xk = (kk == 0) ? xv.x : (kk == 1) ? xv.y : (kk == 2) ? xv.z : xv.w;
            const float* wr = &sA[(k4 * 4 + kk) * F64 + q * 16];
            #pragma unroll
            for (int j4 = 0; j4 < 4; j4++) {
                const float4 w = *(const float4*)(wr + j4 * 4);
                h[4*j4+0] = fmaf(xk, w.x, h[4*j4+0]);
                h[4*j4+1] = fmaf(xk, w.y, h[4*j4+1]);
                h[4*j4+2] = fmaf(xk, w.z, h[4*j4+2]);
                h[4*j4+3] = fmaf(xk, w.w, h[4*j4+3]);
            }
        }
    }

    float s = 0.f;
    #pragma unroll
    for (int j = 0; j < 16; j++) s = fmaf(fmaxf(h[j], 0.f), sw[q * 16 + j], s);

    s += __shfl_xor_sync(0xffffffffu, s, 1, 32);
    s += __shfl_xor_sync(0xffffffffu, s, 2, 32);

    if (valid && q == 0) out[row] = s + __ldg(bv);
}

// ---------------------------------------------------------------------------
static inline int imin(int a, int b) { return a < b ? a : b; }

extern "C" void kernel_launch(void* const* d_in, const int* in_sizes, int n_in,
                              void* d_out, int out_size)
{
    const float* x_state   = (const float*)d_in[0];
    const float* x_task    = (const float*)d_in[1];
    const float* x_actor   = (const float*)d_in[2];
    const float* edge_attr = (const float*)d_in[3];
    const float* We  = (const float*)d_in[4];
    const float* be  = (const float*)d_in[5];
    const float* W1a = (const float*)d_in[6];
    const float* b1a = (const float*)d_in[7];
    const float* W1b = (const float*)d_in[8];
    const float* b1b = (const float*)d_in[9];
    const float* W2a = (const float*)d_in[10];
    const float* b2a = (const float*)d_in[11];
    const float* W2b = (const float*)d_in[12];
    const float* b2b = (const float*)d_in[13];
    const int* src_st = (const int*)d_in[14];
    const int* dst_st = (const int*)d_in[15];
    const int* src_ta = (const int*)d_in[16];
    const int* dst_ta = (const int*)d_in[17];

    const int n_state = in_sizes[0] / F64;
    const int n_task  = in_sizes[1] / F64;
    const int n_actor = in_sizes[2] / F64;
    const int E_st = in_sizes[14];
    const int E_ta = in_sizes[16];

    float *p_h_task, *p_tmp, *p_x1, *p_h2;
    cudaGetSymbolAddress((void**)&p_h_task, g_h_task);
    cudaGetSymbolAddress((void**)&p_tmp,    g_tmp);
    cudaGetSymbolAddress((void**)&p_x1,     g_x1);
    cudaGetSymbolAddress((void**)&p_h2,     g_h2);

    // 0) x_state -> bf16
    convert_xstate_kernel<<<1024, 256>>>(x_state, n_state);

    // 1) residual init
    init_kernel<<<1024, 256>>>(x_task, x_actor, n_task, n_actor);

    // 2) GINEConv message + scatter (bf16 gather)
    {
        int blocks = imin((E_st * 16 + 255) / 256, 148 * 48);
        edge_gine_kernel<<<blocks, 256>>>(edge_attr, We, be, src_st, dst_st, E_st);
    }

    // 3) task MLP: x1 = relu(h @ W1a + b1a) @ W1b + b1b   (4 threads/row)
    {
        int gb = (n_task * 4 + 255) / 256;
        layer64_kernel<<<gb, 256>>>(p_h_task, W1a, b1a, p_tmp, n_task, 1);
        layer64_kernel<<<gb, 256>>>(p_tmp,    W1b, b1b, p_x1,  n_task, 0);
    }

    // 4) GINConv gather + scatter (fp32)
    {
        int blocks = imin((E_ta * 16 + 255) / 256, 148 * 48);
        edge_gin_kernel<<<blocks, 256>>>(src_ta, dst_ta, E_ta);
    }

    // 5) actor MLP + head
    {
        int ga = (n_actor * 4 + 255) / 256;
        mlp_head_kernel<<<ga, 256>>>(p_h2, W2a, b2a, W2b, b2b, (float*)d_out, n_actor);
    }
}

// round 5
// speedup vs baseline: 1.4215x; 1.4215x over previous
#include <cuda_runtime.h>

// ---------------------------------------------------------------------------
// CombinedGoalObsNetwork — R5: R1 edge kernels (measured near L2 roofline)
// + bank-conflict-free register-tiled MLP layers (2 rows x 16 cols / thread).
// ---------------------------------------------------------------------------

#define F64 64
#define NTASK_MAX  32768
#define NACT_MAX   32768

__device__ __align__(16) float g_h_task[NTASK_MAX * F64];
__device__ __align__(16) float g_tmp   [NTASK_MAX * F64];
__device__ __align__(16) float g_x1    [NTASK_MAX * F64];
__device__ __align__(16) float g_h2    [NACT_MAX  * F64];

// ---------------------------------------------------------------------------
// Init: h_task = x_task ; h2 = x_actor (scatter-adds land on the residual)
// ---------------------------------------------------------------------------
__global__ void init_kernel(const float* __restrict__ x_task,
                            const float* __restrict__ x_actor,
                            int n_task, int n_actor)
{
    int tot = gridDim.x * blockDim.x;
    int tid = blockIdx.x * blockDim.x + threadIdx.x;
    int nt4 = n_task * (F64 / 4);
    int na4 = n_actor * (F64 / 4);
    const float4* xt = (const float4*)x_task;
    const float4* xa = (const float4*)x_actor;
    float4* ht = (float4*)g_h_task;
    float4* h2 = (float4*)g_h2;
    for (int i = tid; i < nt4; i += tot) ht[i] = xt[i];
    for (int i = tid; i < na4; i += tot) h2[i] = xa[i];
}

__device__ __forceinline__ void red_add_v4(float* p, float4 v)
{
    asm volatile("red.global.add.v4.f32 [%0], {%1,%2,%3,%4};"
                 :: "l"(p), "f"(v.x), "f"(v.y), "f"(v.z), "f"(v.w)
                 : "memory");
}

// ---------------------------------------------------------------------------
// GINEConv edge kernel: 16 lanes/edge, float4 per lane (fp32 gather).
// ---------------------------------------------------------------------------
__global__ void edge_gine_kernel(const float* __restrict__ x_state,
                                 const float* __restrict__ edge_attr,
                                 const float* __restrict__ We,
                                 const float* __restrict__ be,
                                 const int*   __restrict__ src,
                                 const int*   __restrict__ dst,
                                 int E)
{
    const int lane = threadIdx.x & 15;
    const float4 w0 = __ldg((const float4*)We + lane);
    const float4 w1 = __ldg((const float4*)(We + F64) + lane);
    const float4 bb = __ldg((const float4*)be + lane);

    int g  = (blockIdx.x * blockDim.x + threadIdx.x) >> 4;
    int gs = (gridDim.x * blockDim.x) >> 4;

    #pragma unroll 2
    for (int e = g; e < E; e += gs) {
        const int s = __ldg(src + e);
        const int d = __ldg(dst + e);
        const float2 a = __ldg((const float2*)edge_attr + e);
        const float4 x = __ldg((const float4*)(x_state + (size_t)s * F64) + lane);
        float4 v;
        v.x = fmaxf(fmaf(a.x, w0.x, fmaf(a.y, w1.x, x.x + bb.x)), 0.f);
        v.y = fmaxf(fmaf(a.x, w0.y, fmaf(a.y, w1.y, x.y + bb.y)), 0.f);
        v.z = fmaxf(fmaf(a.x, w0.z, fmaf(a.y, w1.z, x.z + bb.z)), 0.f);
        v.w = fmaxf(fmaf(a.x, w0.w, fmaf(a.y, w1.w, x.w + bb.w)), 0.f);
        red_add_v4(g_h_task + (size_t)d * F64 + lane * 4, v);
    }
}

// ---------------------------------------------------------------------------
// GINConv edge kernel: gather x1 row, scatter-add.
// ---------------------------------------------------------------------------
__global__ void edge_gin_kernel(const int* __restrict__ src,
                                const int* __restrict__ dst,
                                int E)
{
    const int lane = threadIdx.x & 15;
    int g  = (blockIdx.x * blockDim.x + threadIdx.x) >> 4;
    int gs = (gridDim.x * blockDim.x) >> 4;

    #pragma unroll 2
    for (int e = g; e < E; e += gs) {
        const int s = __ldg(src + e);
        const int d = __ldg(dst + e);
        const float4 v = *((const float4*)(g_x1 + (size_t)s * F64) + lane);
        red_add_v4(g_h2 + (size_t)d * F64 + lane * 4, v);
    }
}

// ---------------------------------------------------------------------------
// SMEM layout helpers for the MLP kernels.
//   sW: 4 regions (one per column-quarter q), region q at base q*1032 floats
//       (1024 data + 8 pad) -> bank phase 8q: lanes of a warp (q=0..3) hit
//       disjoint banks, each address a 4-lane quad broadcast. Conflict-free.
//   sX: 64 rows staged, stride 68 floats (272B, 16B-aligned); warp rows
//       r0=0..7 -> phases {0,4,..,28}, r1=r0+32 -> same (68*32 % 32 == 0).
//       Conflict-free.
// ---------------------------------------------------------------------------
#define WREG 1032
#define XSTRIDE 68

__device__ __forceinline__ void fill_w4(float* sW, const float* __restrict__ W, int t)
{
    for (int i = t; i < 4096; i += 128) {
        const int q = i >> 10, rem = i & 1023;
        const int k = rem >> 4, j = rem & 15;
        sW[q * WREG + rem] = __ldg(W + k * F64 + q * 16 + j);
    }
}

__device__ __forceinline__ void fill_x(float* sX, const float* __restrict__ in,
                                       int row_base, int n, int t)
{
    for (int i = t; i < 1024; i += 128) {
        const int r = i >> 4, k4 = i & 15;
        const int gr = row_base + r;
        float4 v = make_float4(0.f, 0.f, 0.f, 0.f);
        if (gr < n) v = __ldg((const float4*)(in + (size_t)gr * F64) + k4);
        *(float4*)(sX + r * XSTRIDE + k4 * 4) = v;
    }
}

// ---------------------------------------------------------------------------
// Dense 64x64 layer. Block = 128 threads, 64 rows. Thread (rp, q) computes
// rows {rp, rp+32} x cols [16q, 16q+16). 32 accumulators, zero bank conflicts.
// ---------------------------------------------------------------------------
__global__ void mlp_layer_kernel(const float* __restrict__ in,
                                 const float* __restrict__ W,
                                 const float* __restrict__ b,
                                 float* __restrict__ out,
                                 int n, int do_relu)
{
    __shared__ float sW[4 * WREG];
    __shared__ float sX[64 * XSTRIDE];
    __shared__ float sb[F64];

    const int t = threadIdx.x;
    const int row_base = blockIdx.x * 64;

    fill_w4(sW, W, t);
    if (t < F64) sb[t] = b[t];
    fill_x(sX, in, row_base, n, t);
    __syncthreads();

    const int q  = t & 3;
    const int r0 = t >> 2;        // 0..31
    const int r1 = r0 + 32;

    float a0[16], a1[16];
    #pragma unroll
    for (int j = 0; j < 16; j++) { a0[j] = sb[q * 16 + j]; a1[j] = a0[j]; }

    const float* wq = sW + q * WREG;
    const float* x0p = sX + r0 * XSTRIDE;
    const float* x1p = sX + r1 * XSTRIDE;

    #pragma unroll 4
    for (int k4 = 0; k4 < 16; k4++) {
        const float4 x0 = *(const float4*)(x0p + k4 * 4);
        const float4 x1 = *(const float4*)(x1p + k4 * 4);
        #pragma unroll
        for (int kk = 0; kk < 4; kk++) {
            const float xk0 = (kk == 0) ? x0.x : (kk == 1) ? x0.y : (kk == 2) ? x0.z : x0.w;
            const float xk1 = (kk == 0) ? x1.x : (kk == 1) ? x1.y : (kk == 2) ? x1.z : x1.w;
            const float* wr = wq + (k4 * 4 + kk) * 16;
            #pragma unroll
            for (int j4 = 0; j4 < 4; j4++) {
                const float4 w = *(const float4*)(wr + 4 * j4);
                a0[4*j4+0] = fmaf(xk0, w.x, a0[4*j4+0]);
                a0[4*j4+1] = fmaf(xk0, w.y, a0[4*j4+1]);
                a0[4*j4+2] = fmaf(xk0, w.z, a0[4*j4+2]);
                a0[4*j4+3] = fmaf(xk0, w.w, a0[4*j4+3]);
                a1[4*j4+0] = fmaf(xk1, w.x, a1[4*j4+0]);
                a1[4*j4+1] = fmaf(xk1, w.y, a1[4*j4+1]);
                a1[4*j4+2] = fmaf(xk1, w.z, a1[4*j4+2]);
                a1[4*j4+3] = fmaf(xk1, w.w, a1[4*j4+3]);
            }
        }
    }

    const int gr0 = row_base + r0;
    const int gr1 = row_base + r1;

    if (gr0 < n) {
        float4* op = (float4*)(out + (size_t)gr0 * F64) + q * 4;
        #pragma unroll
        for (int i = 0; i < 4; i++) {
            float4 v = make_float4(a0[4*i+0], a0[4*i+1], a0[4*i+2], a0[4*i+3]);
            if (do_relu) { v.x = fmaxf(v.x,0.f); v.y = fmaxf(v.y,0.f); v.z = fmaxf(v.z,0.f); v.w = fmaxf(v.w,0.f); }
            op[i] = v;
        }
    }
    if (gr1 < n) {
        float4* op = (float4*)(out + (size_t)gr1 * F64) + q * 4;
        #pragma unroll
        for (int i = 0; i < 4; i++) {
            float4 v = make_float4(a1[4*i+0], a1[4*i+1], a1[4*i+2], a1[4*i+3]);
            if (do_relu) { v.x = fmaxf(v.x,0.f); v.y = fmaxf(v.y,0.f); v.z = fmaxf(v.z,0.f); v.w = fmaxf(v.w,0.f); }
            op[i] = v;
        }
    }
}

// ---------------------------------------------------------------------------
// Fused MLP + head: out[row] = relu(in @ W2a + b2a) @ W2b + b2b (64 -> 1)
// Same tiling; quad shfl-reduce (2 shfls) at the end only.
// ---------------------------------------------------------------------------
__global__ void mlp_head_kernel(const float* __restrict__ in,
                                const float* __restrict__ Wa,
                                const float* __restrict__ ba,
                                const float* __restrict__ wv,
                                const float* __restrict__ bv,
                                float* __restrict__ out, int n)
{
    __shared__ float sW[4 * WREG];
    __shared__ float sX[64 * XSTRIDE];
    __shared__ float sb[F64];
    __shared__ float sw[F64];

    const int t = threadIdx.x;
    const int row_base = blockIdx.x * 64;

    fill_w4(sW, Wa, t);
    if (t < F64) { sb[t] = ba[t]; sw[t] = wv[t]; }
    fill_x(sX, in, row_base, n, t);
    __syncthreads();

    const int q  = t & 3;
    const int r0 = t >> 2;
    const int r1 = r0 + 32;

    float a0[16], a1[16];
    #pragma unroll
    for (int j = 0; j < 16; j++) { a0[j] = sb[q * 16 + j]; a1[j] = a0[j]; }

    const float* wq = sW + q * WREG;
    const float* x0p = sX + r0 * XSTRIDE;
    const float* x1p = sX + r1 * XSTRIDE;

    #pragma unroll 4
    for (int k4 = 0; k4 < 16; k4++) {
        const float4 x0 = *(const float4*)(x0p + k4 * 4);
        const float4 x1 = *(const float4*)(x1p + k4 * 4);
        #pragma unroll
        for (int kk = 0; kk < 4; kk++) {
            const float xk0 = (kk == 0) ? x0.x : (kk == 1) ? x0.y : (kk == 2) ? x0.z : x0.w;
            const float xk1 = (kk == 0) ? x1.x : (kk == 1) ? x1.y : (kk == 2) ? x1.z : x1.w;
            const float* wr = wq + (k4 * 4 + kk) * 16;
            #pragma unroll
            for (int j4 = 0; j4 < 4; j4++) {
                const float4 w = *(const float4*)(wr + 4 * j4);
                a0[4*j4+0] = fmaf(xk0, w.x, a0[4*j4+0]);
                a0[4*j4+1] = fmaf(xk0, w.y, a0[4*j4+1]);
                a0[4*j4+2] = fmaf(xk0, w.z, a0[4*j4+2]);
                a0[4*j4+3] = fmaf(xk0, w.w, a0[4*j4+3]);
                a1[4*j4+0] = fmaf(xk1, w.x, a1[4*j4+0]);
                a1[4*j4+1] = fmaf(xk1, w.y, a1[4*j4+1]);
                a1[4*j4+2] = fmaf(xk1, w.z, a1[4*j4+2]);
                a1[4*j4+3] = fmaf(xk1, w.w, a1[4*j4+3]);
            }
        }
    }

    float s0 = 0.f, s1 = 0.f;
    #pragma unroll
    for (int j = 0; j < 16; j++) {
        const float w = sw[q * 16 + j];
        s0 = fmaf(fmaxf(a0[j], 0.f), w, s0);
        s1 = fmaf(fmaxf(a1[j], 0.f), w, s1);
    }
    // quad lanes are consecutive -> xor-reduce within the quad
    s0 += __shfl_xor_sync(0xffffffffu, s0, 1, 32);
    s0 += __shfl_xor_sync(0xffffffffu, s0, 2, 32);
    s1 += __shfl_xor_sync(0xffffffffu, s1, 1, 32);
    s1 += __shfl_xor_sync(0xffffffffu, s1, 2, 32);

    if (q == 0) {
        const float bias = __ldg(bv);
        const int gr0 = row_base + r0;
        const int gr1 = row_base + r1;
        if (gr0 < n) out[gr0] = s0 + bias;
        if (gr1 < n) out[gr1] = s1 + bias;
    }
}

// ---------------------------------------------------------------------------
static inline int imin(int a, int b) { return a < b ? a : b; }

extern "C" void kernel_launch(void* const* d_in, const int* in_sizes, int n_in,
                              void* d_out, int out_size)
{
    const float* x_state   = (const float*)d_in[0];
    const float* x_task    = (const float*)d_in[1];
    const float* x_actor   = (const float*)d_in[2];
    const float* edge_attr = (const float*)d_in[3];
    const float* We  = (const float*)d_in[4];
    const float* be  = (const float*)d_in[5];
    const float* W1a = (const float*)d_in[6];
    const float* b1a = (const float*)d_in[7];
    const float* W1b = (const float*)d_in[8];
    const float* b1b = (const float*)d_in[9];
    const float* W2a = (const float*)d_in[10];
    const float* b2a = (const float*)d_in[11];
    const float* W2b = (const float*)d_in[12];
    const float* b2b = (const float*)d_in[13];
    const int* src_st = (const int*)d_in[14];
    const int* dst_st = (const int*)d_in[15];
    const int* src_ta = (const int*)d_in[16];
    const int* dst_ta = (const int*)d_in[17];

    const int n_task  = in_sizes[1] / F64;
    const int n_actor = in_sizes[2] / F64;
    const int E_st = in_sizes[14];
    const int E_ta = in_sizes[16];

    float *p_h_task, *p_tmp, *p_x1, *p_h2;
    cudaGetSymbolAddress((void**)&p_h_task, g_h_task);
    cudaGetSymbolAddress((void**)&p_tmp,    g_tmp);
    cudaGetSymbolAddress((void**)&p_x1,     g_x1);
    cudaGetSymbolAddress((void**)&p_h2,     g_h2);

    // 1) residual init
    init_kernel<<<1024, 256>>>(x_task, x_actor, n_task, n_actor);

    // 2) GINEConv message + scatter
    {
        int blocks = imin((E_st * 16 + 255) / 256, 148 * 48);
        edge_gine_kernel<<<blocks, 256>>>(x_state, edge_attr, We, be,
                                          src_st, dst_st, E_st);
    }

    // 3) task MLP: x1 = relu(h @ W1a + b1a) @ W1b + b1b
    {
        int gb = (n_task + 63) / 64;
        mlp_layer_kernel<<<gb, 128>>>(p_h_task, W1a, b1a, p_tmp, n_task, 1);
        mlp_layer_kernel<<<gb, 128>>>(p_tmp,    W1b, b1b, p_x1,  n_task, 0);
    }

    // 4) GINConv gather + scatter
    {
        int blocks = imin((E_ta * 16 + 255) / 256, 148 * 48);
        edge_gin_kernel<<<blocks, 256>>>(src_ta, dst_ta, E_ta);
    }

    // 5) actor MLP + head
    {
        int ga = (n_actor + 63) / 64;
        mlp_head_kernel<<<ga, 128>>>(p_h2, W2a, b2a, W2b, b2b, (float*)d_out, n_actor);
    }
}

// round 6
// speedup vs baseline: 1.4971x; 1.0532x over previous
#include <cuda_runtime.h>

// ---------------------------------------------------------------------------
// CombinedGoalObsNetwork — R6: R1 edge kernels (at L2 roofline) +
// 4-rows/thread MLP layers: W-only SMEM (conflict-free 4-region layout),
// X streamed from global through L1 (quad-broadcast), 64 accumulators.
// ---------------------------------------------------------------------------

#define F64 64
#define NTASK_MAX  32768
#define NACT_MAX   32768

__device__ __align__(16) float g_h_task[NTASK_MAX * F64];
__device__ __align__(16) float g_tmp   [NTASK_MAX * F64];
__device__ __align__(16) float g_x1    [NTASK_MAX * F64];
__device__ __align__(16) float g_h2    [NACT_MAX  * F64];

// ---------------------------------------------------------------------------
// Init: h_task = x_task ; h2 = x_actor (scatter-adds land on the residual)
// ---------------------------------------------------------------------------
__global__ void init_kernel(const float* __restrict__ x_task,
                            const float* __restrict__ x_actor,
                            int n_task, int n_actor)
{
    int tot = gridDim.x * blockDim.x;
    int tid = blockIdx.x * blockDim.x + threadIdx.x;
    int nt4 = n_task * (F64 / 4);
    int na4 = n_actor * (F64 / 4);
    const float4* xt = (const float4*)x_task;
    const float4* xa = (const float4*)x_actor;
    float4* ht = (float4*)g_h_task;
    float4* h2 = (float4*)g_h2;
    for (int i = tid; i < nt4; i += tot) ht[i] = xt[i];
    for (int i = tid; i < na4; i += tot) h2[i] = xa[i];
}

__device__ __forceinline__ void red_add_v4(float* p, float4 v)
{
    asm volatile("red.global.add.v4.f32 [%0], {%1,%2,%3,%4};"
                 :: "l"(p), "f"(v.x), "f"(v.y), "f"(v.z), "f"(v.w)
                 : "memory");
}

// ---------------------------------------------------------------------------
// GINEConv edge kernel: 16 lanes/edge, float4 per lane.
// ---------------------------------------------------------------------------
__global__ void edge_gine_kernel(const float* __restrict__ x_state,
                                 const float* __restrict__ edge_attr,
                                 const float* __restrict__ We,
                                 const float* __restrict__ be,
                                 const int*   __restrict__ src,
                                 const int*   __restrict__ dst,
                                 int E)
{
    const int lane = threadIdx.x & 15;
    const float4 w0 = __ldg((const float4*)We + lane);
    const float4 w1 = __ldg((const float4*)(We + F64) + lane);
    const float4 bb = __ldg((const float4*)be + lane);

    int g  = (blockIdx.x * blockDim.x + threadIdx.x) >> 4;
    int gs = (gridDim.x * blockDim.x) >> 4;

    #pragma unroll 2
    for (int e = g; e < E; e += gs) {
        const int s = __ldg(src + e);
        const int d = __ldg(dst + e);
        const float2 a = __ldg((const float2*)edge_attr + e);
        const float4 x = __ldg((const float4*)(x_state + (size_t)s * F64) + lane);
        float4 v;
        v.x = fmaxf(fmaf(a.x, w0.x, fmaf(a.y, w1.x, x.x + bb.x)), 0.f);
        v.y = fmaxf(fmaf(a.x, w0.y, fmaf(a.y, w1.y, x.y + bb.y)), 0.f);
        v.z = fmaxf(fmaf(a.x, w0.z, fmaf(a.y, w1.z, x.z + bb.z)), 0.f);
        v.w = fmaxf(fmaf(a.x, w0.w, fmaf(a.y, w1.w, x.w + bb.w)), 0.f);
        red_add_v4(g_h_task + (size_t)d * F64 + lane * 4, v);
    }
}

// ---------------------------------------------------------------------------
// GINConv edge kernel: gather x1 row, scatter-add.
// ---------------------------------------------------------------------------
__global__ void edge_gin_kernel(const int* __restrict__ src,
                                const int* __restrict__ dst,
                                int E)
{
    const int lane = threadIdx.x & 15;
    int g  = (blockIdx.x * blockDim.x + threadIdx.x) >> 4;
    int gs = (gridDim.x * blockDim.x) >> 4;

    #pragma unroll 2
    for (int e = g; e < E; e += gs) {
        const int s = __ldg(src + e);
        const int d = __ldg(dst + e);
        const float4 v = *((const float4*)(g_x1 + (size_t)s * F64) + lane);
        red_add_v4(g_h2 + (size_t)d * F64 + lane * 4, v);
    }
}

// ---------------------------------------------------------------------------
// W SMEM: 4 regions (one per column-quarter q), region q at q*1032 floats
// (1024 data + 8 pad). Same-q lanes broadcast; different q -> disjoint banks.
// ---------------------------------------------------------------------------
#define WREG 1032

__device__ __forceinline__ void fill_w4(float* sW, const float* __restrict__ W, int t, int nthr)
{
    for (int i = t; i < 4096; i += nthr) {
        const int q = i >> 10, rem = i & 1023;
        const int k = rem >> 4, j = rem & 15;
        sW[q * WREG + rem] = __ldg(W + k * F64 + q * 16 + j);
    }
}

#define FMA16(acc, xk, w)                          \
    acc[0] = fmaf(xk, w.x, acc[0]);                \
    acc[1] = fmaf(xk, w.y, acc[1]);                \
    acc[2] = fmaf(xk, w.z, acc[2]);                \
    acc[3] = fmaf(xk, w.w, acc[3]);

// ---------------------------------------------------------------------------
// Dense 64x64 layer. Block = 128 threads covering 128 rows.
// Thread (rp = t>>2, q = t&3): rows rp+{0,32,64,96}, cols [16q, 16q+16).
// X from global (L1 quad-broadcast), W from SMEM. 64 accumulators.
// ---------------------------------------------------------------------------
__global__ void mlp_layer_kernel(const float* __restrict__ in,
                                 const float* __restrict__ W,
                                 const float* __restrict__ b,
                                 float* __restrict__ out,
                                 int n, int do_relu)
{
    __shared__ float sW[4 * WREG];
    __shared__ float sb[F64];

    const int t = threadIdx.x;
    fill_w4(sW, W, t, 128);
    if (t < F64) sb[t] = b[t];
    __syncthreads();

    const int q  = t & 3;
    const int rp = t >> 2;                 // 0..31
    const int row_base = blockIdx.x * 128;

    const float4* x0p = (const float4*)(in + (size_t)(row_base + rp      ) * F64);
    const float4* x1p = (const float4*)(in + (size_t)(row_base + rp + 32 ) * F64);
    const float4* x2p = (const float4*)(in + (size_t)(row_base + rp + 64 ) * F64);
    const float4* x3p = (const float4*)(in + (size_t)(row_base + rp + 96 ) * F64);

    float a0[16], a1[16], a2[16], a3[16];
    #pragma unroll
    for (int j = 0; j < 16; j++) {
        const float bj = sb[q * 16 + j];
        a0[j] = bj; a1[j] = bj; a2[j] = bj; a3[j] = bj;
    }

    const float* wq = sW + q * WREG;

    #pragma unroll 4
    for (int k4 = 0; k4 < 16; k4++) {
        const float4 x0 = __ldg(x0p + k4);
        const float4 x1 = __ldg(x1p + k4);
        const float4 x2 = __ldg(x2p + k4);
        const float4 x3 = __ldg(x3p + k4);
        #pragma unroll
        for (int kk = 0; kk < 4; kk++) {
            const float f0 = (kk==0)?x0.x:(kk==1)?x0.y:(kk==2)?x0.z:x0.w;
            const float f1 = (kk==0)?x1.x:(kk==1)?x1.y:(kk==2)?x1.z:x1.w;
            const float f2 = (kk==0)?x2.x:(kk==1)?x2.y:(kk==2)?x2.z:x2.w;
            const float f3 = (kk==0)?x3.x:(kk==1)?x3.y:(kk==2)?x3.z:x3.w;
            const float* wr = wq + (k4 * 4 + kk) * 16;
            #pragma unroll
            for (int j4 = 0; j4 < 4; j4++) {
                const float4 w = *(const float4*)(wr + 4 * j4);
                FMA16((a0 + 4*j4), f0, w);
                FMA16((a1 + 4*j4), f1, w);
                FMA16((a2 + 4*j4), f2, w);
                FMA16((a3 + 4*j4), f3, w);
            }
        }
    }

    float* accs[4] = {a0, a1, a2, a3};
    #pragma unroll
    for (int rr = 0; rr < 4; rr++) {
        const int gr = row_base + rp + rr * 32;
        if (gr < n) {
            float* a = accs[rr];
            float4* op = (float4*)(out + (size_t)gr * F64) + q * 4;
            #pragma unroll
            for (int i = 0; i < 4; i++) {
                float4 v = make_float4(a[4*i+0], a[4*i+1], a[4*i+2], a[4*i+3]);
                if (do_relu) { v.x=fmaxf(v.x,0.f); v.y=fmaxf(v.y,0.f); v.z=fmaxf(v.z,0.f); v.w=fmaxf(v.w,0.f); }
                op[i] = v;
            }
        }
    }
}

// ---------------------------------------------------------------------------
// Fused MLP + head: out[row] = relu(in @ W2a + b2a) @ W2b + b2b (64 -> 1)
// Same 4-rows/thread tiling; quad shfl-reduce epilogue.
// ---------------------------------------------------------------------------
__global__ void mlp_head_kernel(const float* __restrict__ in,
                                const float* __restrict__ Wa,
                                const float* __restrict__ ba,
                                const float* __restrict__ wv,
                                const float* __restrict__ bv,
                                float* __restrict__ out, int n)
{
    __shared__ float sW[4 * WREG];
    __shared__ float sb[F64];
    __shared__ float sw[F64];

    const int t = threadIdx.x;
    fill_w4(sW, Wa, t, 128);
    if (t < F64) { sb[t] = ba[t]; sw[t] = wv[t]; }
    __syncthreads();

    const int q  = t & 3;
    const int rp = t >> 2;
    const int row_base = blockIdx.x * 128;

    const float4* x0p = (const float4*)(in + (size_t)(row_base + rp      ) * F64);
    const float4* x1p = (const float4*)(in + (size_t)(row_base + rp + 32 ) * F64);
    const float4* x2p = (const float4*)(in + (size_t)(row_base + rp + 64 ) * F64);
    const float4* x3p = (const float4*)(in + (size_t)(row_base + rp + 96 ) * F64);

    float a0[16], a1[16], a2[16], a3[16];
    #pragma unroll
    for (int j = 0; j < 16; j++) {
        const float bj = sb[q * 16 + j];
        a0[j] = bj; a1[j] = bj; a2[j] = bj; a3[j] = bj;
    }

    const float* wq = sW + q * WREG;

    #pragma unroll 4
    for (int k4 = 0; k4 < 16; k4++) {
        const float4 x0 = __ldg(x0p + k4);
        const float4 x1 = __ldg(x1p + k4);
        const float4 x2 = __ldg(x2p + k4);
        const float4 x3 = __ldg(x3p + k4);
        #pragma unroll
        for (int kk = 0; kk < 4; kk++) {
            const float f0 = (kk==0)?x0.x:(kk==1)?x0.y:(kk==2)?x0.z:x0.w;
            const float f1 = (kk==0)?x1.x:(kk==1)?x1.y:(kk==2)?x1.z:x1.w;
            const float f2 = (kk==0)?x2.x:(kk==1)?x2.y:(kk==2)?x2.z:x2.w;
            const float f3 = (kk==0)?x3.x:(kk==1)?x3.y:(kk==2)?x3.z:x3.w;
            const float* wr = wq + (k4 * 4 + kk) * 16;
            #pragma unroll
            for (int j4 = 0; j4 < 4; j4++) {
                const float4 w = *(const float4*)(wr + 4 * j4);
                FMA16((a0 + 4*j4), f0, w);
                FMA16((a1 + 4*j4), f1, w);
                FMA16((a2 + 4*j4), f2, w);
                FMA16((a3 + 4*j4), f3, w);
            }
        }
    }

    float s0 = 0.f, s1 = 0.f, s2 = 0.f, s3 = 0.f;
    #pragma unroll
    for (int j = 0; j < 16; j++) {
        const float w = sw[q * 16 + j];
        s0 = fmaf(fmaxf(a0[j], 0.f), w, s0);
        s1 = fmaf(fmaxf(a1[j], 0.f), w, s1);
        s2 = fmaf(fmaxf(a2[j], 0.f), w, s2);
        s3 = fmaf(fmaxf(a3[j], 0.f), w, s3);
    }
    s0 += __shfl_xor_sync(0xffffffffu, s0, 1, 32);
    s0 += __shfl_xor_sync(0xffffffffu, s0, 2, 32);
    s1 += __shfl_xor_sync(0xffffffffu, s1, 1, 32);
    s1 += __shfl_xor_sync(0xffffffffu, s1, 2, 32);
    s2 += __shfl_xor_sync(0xffffffffu, s2, 1, 32);
    s2 += __shfl_xor_sync(0xffffffffu, s2, 2, 32);
    s3 += __shfl_xor_sync(0xffffffffu, s3, 1, 32);
    s3 += __shfl_xor_sync(0xffffffffu, s3, 2, 32);

    if (q == 0) {
        const float bias = __ldg(bv);
        const int g0 = row_base + rp;
        if (g0      < n) out[g0     ] = s0 + bias;
        if (g0 + 32 < n) out[g0 + 32] = s1 + bias;
        if (g0 + 64 < n) out[g0 + 64] = s2 + bias;
        if (g0 + 96 < n) out[g0 + 96] = s3 + bias;
    }
}

// ---------------------------------------------------------------------------
static inline int imin(int a, int b) { return a < b ? a : b; }

extern "C" void kernel_launch(void* const* d_in, const int* in_sizes, int n_in,
                              void* d_out, int out_size)
{
    const float* x_state   = (const float*)d_in[0];
    const float* x_task    = (const float*)d_in[1];
    const float* x_actor   = (const float*)d_in[2];
    const float* edge_attr = (const float*)d_in[3];
    const float* We  = (const float*)d_in[4];
    const float* be  = (const float*)d_in[5];
    const float* W1a = (const float*)d_in[6];
    const float* b1a = (const float*)d_in[7];
    const float* W1b = (const float*)d_in[8];
    const float* b1b = (const float*)d_in[9];
    const float* W2a = (const float*)d_in[10];
    const float* b2a = (const float*)d_in[11];
    const float* W2b = (const float*)d_in[12];
    const float* b2b = (const float*)d_in[13];
    const int* src_st = (const int*)d_in[14];
    const int* dst_st = (const int*)d_in[15];
    const int* src_ta = (const int*)d_in[16];
    const int* dst_ta = (const int*)d_in[17];

    const int n_task  = in_sizes[1] / F64;
    const int n_actor = in_sizes[2] / F64;
    const int E_st = in_sizes[14];
    const int E_ta = in_sizes[16];

    float *p_h_task, *p_tmp, *p_x1, *p_h2;
    cudaGetSymbolAddress((void**)&p_h_task, g_h_task);
    cudaGetSymbolAddress((void**)&p_tmp,    g_tmp);
    cudaGetSymbolAddress((void**)&p_x1,     g_x1);
    cudaGetSymbolAddress((void**)&p_h2,     g_h2);

    // 1) residual init
    init_kernel<<<1024, 256>>>(x_task, x_actor, n_task, n_actor);

    // 2) GINEConv message + scatter
    {
        int blocks = imin((E_st * 16 + 255) / 256, 148 * 48);
        edge_gine_kernel<<<blocks, 256>>>(x_state, edge_attr, We, be,
                                          src_st, dst_st, E_st);
    }

    // 3) task MLP: x1 = relu(h @ W1a + b1a) @ W1b + b1b
    {
        int gb = (n_task + 127) / 128;
        mlp_layer_kernel<<<gb, 128>>>(p_h_task, W1a, b1a, p_tmp, n_task, 1);
        mlp_layer_kernel<<<gb, 128>>>(p_tmp,    W1b, b1b, p_x1,  n_task, 0);
    }

    // 4) GINConv gather + scatter
    {
        int blocks = imin((E_ta * 16 + 255) / 256, 148 * 48);
        edge_gin_kernel<<<blocks, 256>>>(src_ta, dst_ta, E_ta);
    }

    // 5) actor MLP + head
    {
        int ga = (n_actor + 127) / 128;
        mlp_head_kernel<<<ga, 128>>>(p_h2, W2a, b2a, W2b, b2b, (float*)d_out, n_actor);
    }
}